// round 13
// baseline (speedup 1.0000x reference)
#include <cuda_runtime.h>

// EfConv: out[n, k*64+o] = b[o] + sum_{e: dst[e]==n} edge_feat[e,k] * z[src[e], o]
// where z = node_feat @ W^T.
//
// Pipeline:
//   0. zhist_kernel : z = nf @ W^T (64 nodes/block, f32x2 FFMA) + histogram
//   1. scan_kernel  : smem-resident scan (warp-shuffle hierarchy); re-zeros counts
//   2. build_kernel : scatter (src<<8) + ef rows into CSR order (8 edges/thr)
//   3. gather_kernel: warp-per-node, R7-best structure (4-edge groups, z
//                     pipelined one group ahead); z loads via ld.global.cg
//                     (L2-only, no L1 fill) as scalar-pair PTX to avoid the
//                     register bloat that poisoned the R12 hint experiment.

#define MAX_N 50000
#define MAX_E 800000

__device__ float g_z[MAX_N * 64];
__device__ int   g_counts[MAX_N];
__device__ int   g_offsets[MAX_N + 1];
__device__ int   g_cursor[MAX_N];
__device__ int   g_srcs[MAX_E];          // src<<8 (byte offset of z row)
__device__ float g_efs[(size_t)MAX_E * 8];

// ---------------------------------------------------------------------------
__device__ __forceinline__ void ffma2(unsigned long long& d,
                                      unsigned long long a,
                                      unsigned long long b) {
    asm("fma.rn.f32x2 %0, %1, %2, %0;" : "+l"(d) : "l"(a), "l"(b));
}
__device__ __forceinline__ unsigned long long dupf(float v) {
    unsigned long long r;
    asm("mov.b64 %0, {%1, %1};" : "=l"(r) : "r"(__float_as_uint(v)));
    return r;
}
__device__ __forceinline__ float2 unpack2(unsigned long long v) {
    unsigned int lo, hi;
    asm("mov.b64 {%0, %1}, %2;" : "=r"(lo), "=r"(hi) : "l"(v));
    return make_float2(__uint_as_float(lo), __uint_as_float(hi));
}
// L2-only 8-byte load (no L1 allocate), scalar-pair form.
__device__ __forceinline__ float2 ldcg2(const void* p) {
    float x, y;
    asm volatile("ld.global.cg.v2.f32 {%0, %1}, [%2];"
                 : "=f"(x), "=f"(y) : "l"(p));
    return make_float2(x, y);
}

// ---------------------------------------------------------------------------
// z = nf @ W^T, 64 nodes/block, thread = 4 nodes x 2 out-pairs (f32x2).
// Plus grid-stride int4 histogram of dst.
// ---------------------------------------------------------------------------
__global__ __launch_bounds__(256)
void zhist_kernel(const float* __restrict__ nf,
                  const float* __restrict__ W,
                  const int* __restrict__ dst, int N, int E) {
    __shared__ float Ws[64 * 68];    // Ws[i*68+o] = W[o*64+i]
    __shared__ float nfs[64 * 64];
    int tid = threadIdx.x;

#pragma unroll
    for (int it = 0; it < 16; ++it) {
        int idx = it * 256 + tid;            // idx = o*64 + i
        int o = idx >> 6, i = idx & 63;
        Ws[i * 68 + o] = W[idx];
    }

    int nb = blockIdx.x * 64;
#pragma unroll
    for (int it = 0; it < 16; ++it) {
        int idx = it * 256 + tid;
        int n = nb + (idx >> 6);
        nfs[idx] = (n < N) ? nf[(size_t)n * 64 + (idx & 63)] : 0.0f;
    }

    int gs = gridDim.x * 256;
    int quads = (E + 3) >> 2;
    for (int u = blockIdx.x * 256 + tid; u < quads; u += gs) {
        int e4 = u * 4;
        if (e4 + 3 < E) {
            int4 d = *(const int4*)(dst + e4);
            atomicAdd(&g_counts[d.x], 1);
            atomicAdd(&g_counts[d.y], 1);
            atomicAdd(&g_counts[d.z], 1);
            atomicAdd(&g_counts[d.w], 1);
        } else {
            for (int e = e4; e < E; ++e) atomicAdd(&g_counts[dst[e]], 1);
        }
    }
    __syncthreads();

    int ng = tid >> 4;        // node group 0..15
    int ow = tid & 15;        // out quad 0..15
    unsigned long long accp[4][2];
#pragma unroll
    for (int j = 0; j < 4; ++j) { accp[j][0] = 0ull; accp[j][1] = 0ull; }

#pragma unroll 4
    for (int i = 0; i < 64; ++i) {
        ulonglong2 wp = *(const ulonglong2*)(Ws + i * 68 + ow * 4);
        unsigned long long a0 = dupf(nfs[(ng * 4 + 0) * 64 + i]);
        unsigned long long a1 = dupf(nfs[(ng * 4 + 1) * 64 + i]);
        unsigned long long a2 = dupf(nfs[(ng * 4 + 2) * 64 + i]);
        unsigned long long a3 = dupf(nfs[(ng * 4 + 3) * 64 + i]);
        ffma2(accp[0][0], wp.x, a0);  ffma2(accp[0][1], wp.y, a0);
        ffma2(accp[1][0], wp.x, a1);  ffma2(accp[1][1], wp.y, a1);
        ffma2(accp[2][0], wp.x, a2);  ffma2(accp[2][1], wp.y, a2);
        ffma2(accp[3][0], wp.x, a3);  ffma2(accp[3][1], wp.y, a3);
    }

#pragma unroll
    for (int j = 0; j < 4; ++j) {
        int n = nb + ng * 4 + j;
        if (n < N)
            *(ulonglong2*)(g_z + (size_t)n * 64 + ow * 4) =
                make_ulonglong2(accp[j][0], accp[j][1]);
    }
}

// ---------------------------------------------------------------------------
__global__ __launch_bounds__(1024)
void scan_kernel(int N) {
    extern __shared__ int ss[];
    int* s     = ss;          // [N]
    int* wsum  = ss + N;      // [32]
    int t    = threadIdx.x;
    int lane = t & 31;
    int wid  = t >> 5;
    int C = (N + 1023) >> 10;

    for (int i = t; i < N; i += 1024) {
        s[i] = g_counts[i];
        g_counts[i] = 0;
    }
    __syncthreads();

    int base = t * C;
    int sum = 0;
    for (int i = 0; i < C; ++i) {
        int n = base + i;
        if (n < N) sum += s[n];
    }

    int v = sum;
#pragma unroll
    for (int d = 1; d < 32; d <<= 1) {
        int u = __shfl_up_sync(0xffffffffu, v, d);
        if (lane >= d) v += u;
    }
    if (lane == 31) wsum[wid] = v;
    __syncthreads();

    if (wid == 0) {
        int wv = wsum[lane];
#pragma unroll
        for (int d = 1; d < 32; d <<= 1) {
            int u = __shfl_up_sync(0xffffffffu, wv, d);
            if (lane >= d) wv += u;
        }
        wsum[lane] = wv;
    }
    __syncthreads();

    int excl = v - sum + (wid > 0 ? wsum[wid - 1] : 0);
    int total = wsum[31];

    int run = excl;
    for (int i = 0; i < C; ++i) {
        int n = base + i;
        if (n < N) {
            int c = s[n];
            s[n] = run;
            run += c;
        }
    }
    __syncthreads();

    for (int i = t; i < N; i += 1024) {
        int o = s[i];
        g_offsets[i] = o;
        g_cursor[i]  = o;
    }
    if (t == 0) g_offsets[N] = total;
}

// ---------------------------------------------------------------------------
// Scatter src + ef rows into dst-sorted order. 8 edges/thread for MLP.
// ---------------------------------------------------------------------------
__global__ __launch_bounds__(256)
void build_kernel(const int* __restrict__ dst,
                  const int* __restrict__ src,
                  const float* __restrict__ ef, int E) {
    int t = blockIdx.x * 256 + threadIdx.x;
    int e8 = t * 8;
    if (e8 + 7 < E) {
        int4 d0 = *(const int4*)(dst + e8);
        int4 d1 = *(const int4*)(dst + e8 + 4);
        int4 s0 = *(const int4*)(src + e8);
        int4 s1 = *(const int4*)(src + e8 + 4);
        int p0 = atomicAdd(&g_cursor[d0.x], 1);
        int p1 = atomicAdd(&g_cursor[d0.y], 1);
        int p2 = atomicAdd(&g_cursor[d0.z], 1);
        int p3 = atomicAdd(&g_cursor[d0.w], 1);
        int p4 = atomicAdd(&g_cursor[d1.x], 1);
        int p5 = atomicAdd(&g_cursor[d1.y], 1);
        int p6 = atomicAdd(&g_cursor[d1.z], 1);
        int p7 = atomicAdd(&g_cursor[d1.w], 1);
        const float4* p = (const float4*)(ef + (size_t)e8 * 8);
        g_srcs[p0] = s0.x << 8; g_srcs[p1] = s0.y << 8;
        g_srcs[p2] = s0.z << 8; g_srcs[p3] = s0.w << 8;
        g_srcs[p4] = s1.x << 8; g_srcs[p5] = s1.y << 8;
        g_srcs[p6] = s1.z << 8; g_srcs[p7] = s1.w << 8;
        int pos[8] = {p0, p1, p2, p3, p4, p5, p6, p7};
#pragma unroll
        for (int j = 0; j < 8; ++j) {
            float4 a = p[j * 2];
            float4 b = p[j * 2 + 1];
            float4* q = (float4*)(g_efs + (size_t)pos[j] * 8);
            q[0] = a;
            q[1] = b;
        }
    } else {
        for (int e = e8; e < E; ++e) {
            int pp = atomicAdd(&g_cursor[dst[e]], 1);
            g_srcs[pp] = src[e] << 8;
            const float4* p = (const float4*)(ef + (size_t)e * 8);
            float4 a = p[0], b = p[1];
            float4* q = (float4*)(g_efs + (size_t)pp * 8);
            q[0] = a; q[1] = b;
        }
    }
}

// ---------------------------------------------------------------------------
// Warp per node (R7-best structure). acc[kp] = (out[2kp][c0], out[2kp+1][c0])
// packed f32x2, acc[4+kp] for c1, (c0,c1) = (2*lane, 2*lane+1).
// Per 32-edge batch: lane-parallel resolve into conflict-free smem; inner
// loop over 4-edge groups with z loads (ld.global.cg -> no L1 fill)
// pipelined one group ahead (clamped index, branch-free).
// ---------------------------------------------------------------------------
__global__ __launch_bounds__(256)
void gather_kernel(const float* __restrict__ bias,
                   float* __restrict__ out, int N) {
    __shared__ __align__(16) float4 sA[8][32];
    __shared__ __align__(16) float4 sB[8][32];
    __shared__ __align__(16) int sOf[8][32];
    int wblk = threadIdx.x >> 5;
    int w    = (blockIdx.x * blockDim.x + threadIdx.x) >> 5;
    int lane = threadIdx.x & 31;
    if (w >= N) return;

    int start = g_offsets[w];
    int cnt   = g_offsets[w + 1] - start;

    float2 bv = ((const float2*)bias)[lane];
    unsigned long long acc[8];
#pragma unroll
    for (int kp = 0; kp < 4; ++kp) {
        acc[kp]     = dupf(bv.x);
        acc[4 + kp] = dupf(bv.y);
    }

    const char* zl = (const char*)g_z + lane * 8;

    for (int base = 0; base < cnt; base += 32) {
        int m = min(32, cnt - base);
        int idx = start + base + lane;
        int off = 0;
        float4 ea = make_float4(0.f, 0.f, 0.f, 0.f);
        float4 eb = make_float4(0.f, 0.f, 0.f, 0.f);
        if (lane < m) {
            off = g_srcs[idx];
            const float4* p = (const float4*)(g_efs + (size_t)idx * 8);
            ea = p[0];
            eb = p[1];
        }
        sOf[wblk][lane] = off;
        sA[wblk][lane] = ea;
        sB[wblk][lane] = eb;
        __syncwarp();

        int groups = (m + 3) >> 2;
        int last = groups - 1;

        int4 o4 = *(const int4*)&sOf[wblk][0];
        float2 z0 = ldcg2(zl + o4.x);
        float2 z1 = ldcg2(zl + o4.y);
        float2 z2 = ldcg2(zl + o4.z);
        float2 z3 = ldcg2(zl + o4.w);

        for (int g = 0; g < groups; ++g) {
            int gn = (g < last) ? g + 1 : last;
            int4 o4n = *(const int4*)&sOf[wblk][gn * 4];
            float2 y0 = ldcg2(zl + o4n.x);
            float2 y1 = ldcg2(zl + o4n.y);
            float2 y2 = ldcg2(zl + o4n.z);
            float2 y3 = ldcg2(zl + o4n.w);

#pragma unroll
            for (int j = 0; j < 4; ++j) {
                float2 zj = (j == 0) ? z0 : (j == 1) ? z1 : (j == 2) ? z2 : z3;
                int e = g * 4 + j;
                ulonglong2 eA = *(const ulonglong2*)&sA[wblk][e];
                ulonglong2 eB = *(const ulonglong2*)&sB[wblk][e];
                unsigned long long zx = dupf(zj.x);
                unsigned long long zy = dupf(zj.y);
                ffma2(acc[0], eA.x, zx);  ffma2(acc[4], eA.x, zy);
                ffma2(acc[1], eA.y, zx);  ffma2(acc[5], eA.y, zy);
                ffma2(acc[2], eB.x, zx);  ffma2(acc[6], eB.x, zy);
                ffma2(acc[3], eB.y, zx);  ffma2(acc[7], eB.y, zy);
            }
            z0 = y0; z1 = y1; z2 = y2; z3 = y3;
        }
        __syncwarp();
    }

    float* op = out + (size_t)w * 512 + 2 * lane;
#pragma unroll
    for (int kp = 0; kp < 4; ++kp) {
        float2 lo = unpack2(acc[kp]);
        float2 hi = unpack2(acc[4 + kp]);
        *(float2*)(op + (2 * kp) * 64)     = make_float2(lo.x, hi.x);
        *(float2*)(op + (2 * kp + 1) * 64) = make_float2(lo.y, hi.y);
    }
}

// ---------------------------------------------------------------------------
extern "C" void kernel_launch(void* const* d_in, const int* in_sizes, int n_in,
                              void* d_out, int out_size) {
    const float* node_feat = (const float*)d_in[0];
    const float* edge_feat = (const float*)d_in[1];
    const float* W         = (const float*)d_in[2];
    const float* b         = (const float*)d_in[3];
    const int*   src       = (const int*)d_in[4];
    const int*   dst       = (const int*)d_in[5];
    float*       out       = (float*)d_out;

    int N = in_sizes[0] / 64;
    int E = in_sizes[4];

    size_t scan_smem = (size_t)(N + 32) * sizeof(int);
    cudaFuncSetAttribute(scan_kernel,
                         cudaFuncAttributeMaxDynamicSharedMemorySize,
                         (int)scan_smem);

    int zb = (N + 63) / 64;
    zhist_kernel<<<zb, 256>>>(node_feat, W, dst, N, E);
    scan_kernel<<<1, 1024, scan_smem>>>(N);
    build_kernel<<<((E + 7) / 8 + 255) / 256, 256>>>(dst, src, edge_feat, E);
    gather_kernel<<<(N * 32 + 255) / 256, 256>>>(b, out, N);
}

// round 14
// speedup vs baseline: 1.1161x; 1.1161x over previous
#include <cuda_runtime.h>

// EfConv: out[n, k*64+o] = b[o] + sum_{e: dst[e]==n} edge_feat[e,k] * z[src[e], o]
// where z = node_feat @ W^T.
//
// Pipeline (multi-stream fork/join inside graph capture):
//   main stream : hist -> scan -> build -> [join] -> gather
//   side stream : z_kernel (GEMM) runs CONCURRENTLY with hist+scan+build
// z is only consumed by gather, so the ~15-20us GEMM is hidden behind the
// latency-bound CSR construction path.

#define MAX_N 50000
#define MAX_E 800000

__device__ float g_z[MAX_N * 64];
__device__ int   g_counts[MAX_N];
__device__ int   g_offsets[MAX_N + 1];
__device__ int   g_cursor[MAX_N];
__device__ int   g_srcs[MAX_E];          // src<<8 (byte offset of z row)
__device__ float g_efs[(size_t)MAX_E * 8];

// ---------------------------------------------------------------------------
__device__ __forceinline__ void ffma2(unsigned long long& d,
                                      unsigned long long a,
                                      unsigned long long b) {
    asm("fma.rn.f32x2 %0, %1, %2, %0;" : "+l"(d) : "l"(a), "l"(b));
}
__device__ __forceinline__ unsigned long long dupf(float v) {
    unsigned long long r;
    asm("mov.b64 %0, {%1, %1};" : "=l"(r) : "r"(__float_as_uint(v)));
    return r;
}
__device__ __forceinline__ float2 unpack2(unsigned long long v) {
    unsigned int lo, hi;
    asm("mov.b64 {%0, %1}, %2;" : "=r"(lo), "=r"(hi) : "l"(v));
    return make_float2(__uint_as_float(lo), __uint_as_float(hi));
}

// ---------------------------------------------------------------------------
// z = nf @ W^T, 64 nodes/block, thread = 4 nodes x 2 out-pairs (f32x2).
// ---------------------------------------------------------------------------
__global__ __launch_bounds__(256)
void z_kernel(const float* __restrict__ nf,
              const float* __restrict__ W, int N) {
    __shared__ float Ws[64 * 68];    // Ws[i*68+o] = W[o*64+i]
    __shared__ float nfs[64 * 64];
    int tid = threadIdx.x;

#pragma unroll
    for (int it = 0; it < 16; ++it) {
        int idx = it * 256 + tid;            // idx = o*64 + i
        int o = idx >> 6, i = idx & 63;
        Ws[i * 68 + o] = W[idx];
    }

    int nb = blockIdx.x * 64;
#pragma unroll
    for (int it = 0; it < 16; ++it) {
        int idx = it * 256 + tid;
        int n = nb + (idx >> 6);
        nfs[idx] = (n < N) ? nf[(size_t)n * 64 + (idx & 63)] : 0.0f;
    }
    __syncthreads();

    int ng = tid >> 4;        // node group 0..15
    int ow = tid & 15;        // out quad 0..15
    unsigned long long accp[4][2];
#pragma unroll
    for (int j = 0; j < 4; ++j) { accp[j][0] = 0ull; accp[j][1] = 0ull; }

#pragma unroll 4
    for (int i = 0; i < 64; ++i) {
        ulonglong2 wp = *(const ulonglong2*)(Ws + i * 68 + ow * 4);
        unsigned long long a0 = dupf(nfs[(ng * 4 + 0) * 64 + i]);
        unsigned long long a1 = dupf(nfs[(ng * 4 + 1) * 64 + i]);
        unsigned long long a2 = dupf(nfs[(ng * 4 + 2) * 64 + i]);
        unsigned long long a3 = dupf(nfs[(ng * 4 + 3) * 64 + i]);
        ffma2(accp[0][0], wp.x, a0);  ffma2(accp[0][1], wp.y, a0);
        ffma2(accp[1][0], wp.x, a1);  ffma2(accp[1][1], wp.y, a1);
        ffma2(accp[2][0], wp.x, a2);  ffma2(accp[2][1], wp.y, a2);
        ffma2(accp[3][0], wp.x, a3);  ffma2(accp[3][1], wp.y, a3);
    }

#pragma unroll
    for (int j = 0; j < 4; ++j) {
        int n = nb + ng * 4 + j;
        if (n < N)
            *(ulonglong2*)(g_z + (size_t)n * 64 + ow * 4) =
                make_ulonglong2(accp[j][0], accp[j][1]);
    }
}

// ---------------------------------------------------------------------------
__global__ __launch_bounds__(256)
void hist_kernel(const int* __restrict__ dst, int E) {
    int t = blockIdx.x * 256 + threadIdx.x;
    int e4 = t * 4;
    if (e4 + 3 < E) {
        int4 d = *(const int4*)(dst + e4);
        atomicAdd(&g_counts[d.x], 1);
        atomicAdd(&g_counts[d.y], 1);
        atomicAdd(&g_counts[d.z], 1);
        atomicAdd(&g_counts[d.w], 1);
    } else {
        for (int e = e4; e < E; ++e) atomicAdd(&g_counts[dst[e]], 1);
    }
}

// ---------------------------------------------------------------------------
__global__ __launch_bounds__(1024)
void scan_kernel(int N) {
    extern __shared__ int ss[];
    int* s     = ss;          // [N]
    int* wsum  = ss + N;      // [32]
    int t    = threadIdx.x;
    int lane = t & 31;
    int wid  = t >> 5;
    int C = (N + 1023) >> 10;

    for (int i = t; i < N; i += 1024) {
        s[i] = g_counts[i];
        g_counts[i] = 0;
    }
    __syncthreads();

    int base = t * C;
    int sum = 0;
    for (int i = 0; i < C; ++i) {
        int n = base + i;
        if (n < N) sum += s[n];
    }

    int v = sum;
#pragma unroll
    for (int d = 1; d < 32; d <<= 1) {
        int u = __shfl_up_sync(0xffffffffu, v, d);
        if (lane >= d) v += u;
    }
    if (lane == 31) wsum[wid] = v;
    __syncthreads();

    if (wid == 0) {
        int wv = wsum[lane];
#pragma unroll
        for (int d = 1; d < 32; d <<= 1) {
            int u = __shfl_up_sync(0xffffffffu, wv, d);
            if (lane >= d) wv += u;
        }
        wsum[lane] = wv;
    }
    __syncthreads();

    int excl = v - sum + (wid > 0 ? wsum[wid - 1] : 0);
    int total = wsum[31];

    int run = excl;
    for (int i = 0; i < C; ++i) {
        int n = base + i;
        if (n < N) {
            int c = s[n];
            s[n] = run;
            run += c;
        }
    }
    __syncthreads();

    for (int i = t; i < N; i += 1024) {
        int o = s[i];
        g_offsets[i] = o;
        g_cursor[i]  = o;
    }
    if (t == 0) g_offsets[N] = total;
}

// ---------------------------------------------------------------------------
// Scatter src + ef rows into dst-sorted order. 8 edges/thread for MLP.
// ---------------------------------------------------------------------------
__global__ __launch_bounds__(256)
void build_kernel(const int* __restrict__ dst,
                  const int* __restrict__ src,
                  const float* __restrict__ ef, int E) {
    int t = blockIdx.x * 256 + threadIdx.x;
    int e8 = t * 8;
    if (e8 + 7 < E) {
        int4 d0 = *(const int4*)(dst + e8);
        int4 d1 = *(const int4*)(dst + e8 + 4);
        int4 s0 = *(const int4*)(src + e8);
        int4 s1 = *(const int4*)(src + e8 + 4);
        int p0 = atomicAdd(&g_cursor[d0.x], 1);
        int p1 = atomicAdd(&g_cursor[d0.y], 1);
        int p2 = atomicAdd(&g_cursor[d0.z], 1);
        int p3 = atomicAdd(&g_cursor[d0.w], 1);
        int p4 = atomicAdd(&g_cursor[d1.x], 1);
        int p5 = atomicAdd(&g_cursor[d1.y], 1);
        int p6 = atomicAdd(&g_cursor[d1.z], 1);
        int p7 = atomicAdd(&g_cursor[d1.w], 1);
        const float4* p = (const float4*)(ef + (size_t)e8 * 8);
        g_srcs[p0] = s0.x << 8; g_srcs[p1] = s0.y << 8;
        g_srcs[p2] = s0.z << 8; g_srcs[p3] = s0.w << 8;
        g_srcs[p4] = s1.x << 8; g_srcs[p5] = s1.y << 8;
        g_srcs[p6] = s1.z << 8; g_srcs[p7] = s1.w << 8;
        int pos[8] = {p0, p1, p2, p3, p4, p5, p6, p7};
#pragma unroll
        for (int j = 0; j < 8; ++j) {
            float4 a = p[j * 2];
            float4 b = p[j * 2 + 1];
            float4* q = (float4*)(g_efs + (size_t)pos[j] * 8);
            q[0] = a;
            q[1] = b;
        }
    } else {
        for (int e = e8; e < E; ++e) {
            int pp = atomicAdd(&g_cursor[dst[e]], 1);
            g_srcs[pp] = src[e] << 8;
            const float4* p = (const float4*)(ef + (size_t)e * 8);
            float4 a = p[0], b = p[1];
            float4* q = (float4*)(g_efs + (size_t)pp * 8);
            q[0] = a; q[1] = b;
        }
    }
}

// ---------------------------------------------------------------------------
// Warp per node (R8-best, measured 43.7us). acc[kp] = (out[2kp][c0],
// out[2kp+1][c0]) packed f32x2, acc[4+kp] for c1, (c0,c1)=(2*lane,2*lane+1).
// Per 32-edge batch: lane-parallel resolve into conflict-free smem; inner
// loop over 4-edge groups with z loads pipelined one group ahead.
// ---------------------------------------------------------------------------
__global__ __launch_bounds__(256)
void gather_kernel(const float* __restrict__ bias,
                   float* __restrict__ out, int N) {
    __shared__ __align__(16) float4 sA[8][32];
    __shared__ __align__(16) float4 sB[8][32];
    __shared__ __align__(16) int sOf[8][32];
    int wblk = threadIdx.x >> 5;
    int w    = (blockIdx.x * blockDim.x + threadIdx.x) >> 5;
    int lane = threadIdx.x & 31;
    if (w >= N) return;

    int start = g_offsets[w];
    int cnt   = g_offsets[w + 1] - start;

    float2 bv = ((const float2*)bias)[lane];
    unsigned long long acc[8];
#pragma unroll
    for (int kp = 0; kp < 4; ++kp) {
        acc[kp]     = dupf(bv.x);
        acc[4 + kp] = dupf(bv.y);
    }

    const char* zl = (const char*)g_z + lane * 8;

    for (int base = 0; base < cnt; base += 32) {
        int m = min(32, cnt - base);
        int idx = start + base + lane;
        int off = 0;
        float4 ea = make_float4(0.f, 0.f, 0.f, 0.f);
        float4 eb = make_float4(0.f, 0.f, 0.f, 0.f);
        if (lane < m) {
            off = g_srcs[idx];
            const float4* p = (const float4*)(g_efs + (size_t)idx * 8);
            ea = p[0];
            eb = p[1];
        }
        sOf[wblk][lane] = off;
        sA[wblk][lane] = ea;
        sB[wblk][lane] = eb;
        __syncwarp();

        int groups = (m + 3) >> 2;
        int last = groups - 1;

        int4 o4 = *(const int4*)&sOf[wblk][0];
        float2 z0 = *(const float2*)(zl + o4.x);
        float2 z1 = *(const float2*)(zl + o4.y);
        float2 z2 = *(const float2*)(zl + o4.z);
        float2 z3 = *(const float2*)(zl + o4.w);

        for (int g = 0; g < groups; ++g) {
            int gn = (g < last) ? g + 1 : last;
            int4 o4n = *(const int4*)&sOf[wblk][gn * 4];
            float2 y0 = *(const float2*)(zl + o4n.x);
            float2 y1 = *(const float2*)(zl + o4n.y);
            float2 y2 = *(const float2*)(zl + o4n.z);
            float2 y3 = *(const float2*)(zl + o4n.w);

#pragma unroll
            for (int j = 0; j < 4; ++j) {
                float2 zj = (j == 0) ? z0 : (j == 1) ? z1 : (j == 2) ? z2 : z3;
                int e = g * 4 + j;
                ulonglong2 eA = *(const ulonglong2*)&sA[wblk][e];
                ulonglong2 eB = *(const ulonglong2*)&sB[wblk][e];
                unsigned long long zx = dupf(zj.x);
                unsigned long long zy = dupf(zj.y);
                ffma2(acc[0], eA.x, zx);  ffma2(acc[4], eA.x, zy);
                ffma2(acc[1], eA.y, zx);  ffma2(acc[5], eA.y, zy);
                ffma2(acc[2], eB.x, zx);  ffma2(acc[6], eB.x, zy);
                ffma2(acc[3], eB.y, zx);  ffma2(acc[7], eB.y, zy);
            }
            z0 = y0; z1 = y1; z2 = y2; z3 = y3;
        }
        __syncwarp();
    }

    float* op = out + (size_t)w * 512 + 2 * lane;
#pragma unroll
    for (int kp = 0; kp < 4; ++kp) {
        float2 lo = unpack2(acc[kp]);
        float2 hi = unpack2(acc[4 + kp]);
        *(float2*)(op + (2 * kp) * 64)     = make_float2(lo.x, hi.x);
        *(float2*)(op + (2 * kp + 1) * 64) = make_float2(lo.y, hi.y);
    }
}

// ---------------------------------------------------------------------------
extern "C" void kernel_launch(void* const* d_in, const int* in_sizes, int n_in,
                              void* d_out, int out_size) {
    const float* node_feat = (const float*)d_in[0];
    const float* edge_feat = (const float*)d_in[1];
    const float* W         = (const float*)d_in[2];
    const float* b         = (const float*)d_in[3];
    const int*   src       = (const int*)d_in[4];
    const int*   dst       = (const int*)d_in[5];
    float*       out       = (float*)d_out;

    int N = in_sizes[0] / 64;
    int E = in_sizes[4];

    // one-time infra (no device memory): side stream + fork/join events
    static cudaStream_t s_side = nullptr;
    static cudaEvent_t  ev_fork = nullptr, ev_join = nullptr;
    if (s_side == nullptr) {
        if (cudaStreamCreateWithFlags(&s_side, cudaStreamNonBlocking)
                != cudaSuccess) s_side = nullptr;
        if (s_side) {
            cudaEventCreateWithFlags(&ev_fork, cudaEventDisableTiming);
            cudaEventCreateWithFlags(&ev_join, cudaEventDisableTiming);
        }
    }

    size_t scan_smem = (size_t)(N + 32) * sizeof(int);
    cudaFuncSetAttribute(scan_kernel,
                         cudaFuncAttributeMaxDynamicSharedMemorySize,
                         (int)scan_smem);

    int zb = (N + 63) / 64;

    if (s_side) {
        // fork: z-GEMM on side stream, overlapped with CSR construction
        cudaEventRecord(ev_fork, 0);
        cudaStreamWaitEvent(s_side, ev_fork, 0);
        z_kernel<<<zb, 256, 0, s_side>>>(node_feat, W, N);
        cudaEventRecord(ev_join, s_side);

        hist_kernel<<<((E + 3) / 4 + 255) / 256, 256>>>(dst, E);
        scan_kernel<<<1, 1024, scan_smem>>>(N);
        build_kernel<<<((E + 7) / 8 + 255) / 256, 256>>>(dst, src, edge_feat, E);

        cudaStreamWaitEvent(0, ev_join, 0);   // join before gather (needs z)
        gather_kernel<<<(N * 32 + 255) / 256, 256>>>(b, out, N);
    } else {
        // fallback: sequential
        z_kernel<<<zb, 256>>>(node_feat, W, N);
        hist_kernel<<<((E + 3) / 4 + 255) / 256, 256>>>(dst, E);
        scan_kernel<<<1, 1024, scan_smem>>>(N);
        build_kernel<<<((E + 7) / 8 + 255) / 256, 256>>>(dst, src, edge_feat, E);
        gather_kernel<<<(N * 32 + 255) / 256, 256>>>(b, out, N);
    }
}

// round 15
// speedup vs baseline: 1.2287x; 1.1009x over previous
#include <cuda_runtime.h>

// EfConv: out[n, k*64+o] = b[o] + sum_{e: dst[e]==n} edge_feat[e,k] * z[src[e], o]
// where z = node_feat @ W^T.
//
// Pipeline (multi-stream fork/join inside graph capture):
//   main stream : hist -> scan -> build(1 edge/thr) -> [join] -> gather
//   side stream : z_kernel (GEMM) concurrent with hist+scan+build
// Build uses ONE edge per thread (grid 3125): max thread-parallelism covers
// the atomic->scatter latency chain far better than per-thread MLP widening
// (measured 25.8us vs 34.7us at 8 edges/thr).

#define MAX_N 50000
#define MAX_E 800000

__device__ float g_z[MAX_N * 64];
__device__ int   g_counts[MAX_N];
__device__ int   g_offsets[MAX_N + 1];
__device__ int   g_cursor[MAX_N];
__device__ int   g_srcs[MAX_E];          // src<<8 (byte offset of z row)
__device__ float g_efs[(size_t)MAX_E * 8];

// ---------------------------------------------------------------------------
__device__ __forceinline__ void ffma2(unsigned long long& d,
                                      unsigned long long a,
                                      unsigned long long b) {
    asm("fma.rn.f32x2 %0, %1, %2, %0;" : "+l"(d) : "l"(a), "l"(b));
}
__device__ __forceinline__ unsigned long long dupf(float v) {
    unsigned long long r;
    asm("mov.b64 %0, {%1, %1};" : "=l"(r) : "r"(__float_as_uint(v)));
    return r;
}
__device__ __forceinline__ float2 unpack2(unsigned long long v) {
    unsigned int lo, hi;
    asm("mov.b64 {%0, %1}, %2;" : "=r"(lo), "=r"(hi) : "l"(v));
    return make_float2(__uint_as_float(lo), __uint_as_float(hi));
}

// ---------------------------------------------------------------------------
// z = nf @ W^T, 64 nodes/block, thread = 4 nodes x 2 out-pairs (f32x2).
// ---------------------------------------------------------------------------
__global__ __launch_bounds__(256)
void z_kernel(const float* __restrict__ nf,
              const float* __restrict__ W, int N) {
    __shared__ float Ws[64 * 68];    // Ws[i*68+o] = W[o*64+i]
    __shared__ float nfs[64 * 64];
    int tid = threadIdx.x;

#pragma unroll
    for (int it = 0; it < 16; ++it) {
        int idx = it * 256 + tid;            // idx = o*64 + i
        int o = idx >> 6, i = idx & 63;
        Ws[i * 68 + o] = W[idx];
    }

    int nb = blockIdx.x * 64;
#pragma unroll
    for (int it = 0; it < 16; ++it) {
        int idx = it * 256 + tid;
        int n = nb + (idx >> 6);
        nfs[idx] = (n < N) ? nf[(size_t)n * 64 + (idx & 63)] : 0.0f;
    }
    __syncthreads();

    int ng = tid >> 4;        // node group 0..15
    int ow = tid & 15;        // out quad 0..15
    unsigned long long accp[4][2];
#pragma unroll
    for (int j = 0; j < 4; ++j) { accp[j][0] = 0ull; accp[j][1] = 0ull; }

#pragma unroll 4
    for (int i = 0; i < 64; ++i) {
        ulonglong2 wp = *(const ulonglong2*)(Ws + i * 68 + ow * 4);
        unsigned long long a0 = dupf(nfs[(ng * 4 + 0) * 64 + i]);
        unsigned long long a1 = dupf(nfs[(ng * 4 + 1) * 64 + i]);
        unsigned long long a2 = dupf(nfs[(ng * 4 + 2) * 64 + i]);
        unsigned long long a3 = dupf(nfs[(ng * 4 + 3) * 64 + i]);
        ffma2(accp[0][0], wp.x, a0);  ffma2(accp[0][1], wp.y, a0);
        ffma2(accp[1][0], wp.x, a1);  ffma2(accp[1][1], wp.y, a1);
        ffma2(accp[2][0], wp.x, a2);  ffma2(accp[2][1], wp.y, a2);
        ffma2(accp[3][0], wp.x, a3);  ffma2(accp[3][1], wp.y, a3);
    }

#pragma unroll
    for (int j = 0; j < 4; ++j) {
        int n = nb + ng * 4 + j;
        if (n < N)
            *(ulonglong2*)(g_z + (size_t)n * 64 + ow * 4) =
                make_ulonglong2(accp[j][0], accp[j][1]);
    }
}

// ---------------------------------------------------------------------------
__global__ __launch_bounds__(256)
void hist_kernel(const int* __restrict__ dst, int E) {
    int t = blockIdx.x * 256 + threadIdx.x;
    int e4 = t * 4;
    if (e4 + 3 < E) {
        int4 d = *(const int4*)(dst + e4);
        atomicAdd(&g_counts[d.x], 1);
        atomicAdd(&g_counts[d.y], 1);
        atomicAdd(&g_counts[d.z], 1);
        atomicAdd(&g_counts[d.w], 1);
    } else {
        for (int e = e4; e < E; ++e) atomicAdd(&g_counts[dst[e]], 1);
    }
}

// ---------------------------------------------------------------------------
__global__ __launch_bounds__(1024)
void scan_kernel(int N) {
    extern __shared__ int ss[];
    int* s     = ss;          // [N]
    int* wsum  = ss + N;      // [32]
    int t    = threadIdx.x;
    int lane = t & 31;
    int wid  = t >> 5;
    int C = (N + 1023) >> 10;

    for (int i = t; i < N; i += 1024) {
        s[i] = g_counts[i];
        g_counts[i] = 0;
    }
    __syncthreads();

    int base = t * C;
    int sum = 0;
    for (int i = 0; i < C; ++i) {
        int n = base + i;
        if (n < N) sum += s[n];
    }

    int v = sum;
#pragma unroll
    for (int d = 1; d < 32; d <<= 1) {
        int u = __shfl_up_sync(0xffffffffu, v, d);
        if (lane >= d) v += u;
    }
    if (lane == 31) wsum[wid] = v;
    __syncthreads();

    if (wid == 0) {
        int wv = wsum[lane];
#pragma unroll
        for (int d = 1; d < 32; d <<= 1) {
            int u = __shfl_up_sync(0xffffffffu, wv, d);
            if (lane >= d) wv += u;
        }
        wsum[lane] = wv;
    }
    __syncthreads();

    int excl = v - sum + (wid > 0 ? wsum[wid - 1] : 0);
    int total = wsum[31];

    int run = excl;
    for (int i = 0; i < C; ++i) {
        int n = base + i;
        if (n < N) {
            int c = s[n];
            s[n] = run;
            run += c;
        }
    }
    __syncthreads();

    for (int i = t; i < N; i += 1024) {
        int o = s[i];
        g_offsets[i] = o;
        g_cursor[i]  = o;
    }
    if (t == 0) g_offsets[N] = total;
}

// ---------------------------------------------------------------------------
// Scatter src + ef row into dst-sorted order. ONE edge per thread:
// max thread-level parallelism covers the atomic latency (measured best).
// ---------------------------------------------------------------------------
__global__ __launch_bounds__(256)
void build_kernel(const int* __restrict__ dst,
                  const int* __restrict__ src,
                  const float* __restrict__ ef, int E) {
    int e = blockIdx.x * 256 + threadIdx.x;
    if (e < E) {
        int d = dst[e];
        int s = src[e];
        const float4* p = (const float4*)(ef + (size_t)e * 8);
        float4 a = p[0];
        float4 c = p[1];
        int pos = atomicAdd(&g_cursor[d], 1);
        g_srcs[pos] = s << 8;
        float4* q = (float4*)(g_efs + (size_t)pos * 8);
        q[0] = a;
        q[1] = c;
    }
}

// ---------------------------------------------------------------------------
// Warp per node (R8-best, measured 43.7us). acc[kp] = (out[2kp][c0],
// out[2kp+1][c0]) packed f32x2, acc[4+kp] for c1, (c0,c1)=(2*lane,2*lane+1).
// Per 32-edge batch: lane-parallel resolve into conflict-free smem; inner
// loop over 4-edge groups with z loads pipelined one group ahead.
// ---------------------------------------------------------------------------
__global__ __launch_bounds__(256)
void gather_kernel(const float* __restrict__ bias,
                   float* __restrict__ out, int N) {
    __shared__ __align__(16) float4 sA[8][32];
    __shared__ __align__(16) float4 sB[8][32];
    __shared__ __align__(16) int sOf[8][32];
    int wblk = threadIdx.x >> 5;
    int w    = (blockIdx.x * blockDim.x + threadIdx.x) >> 5;
    int lane = threadIdx.x & 31;
    if (w >= N) return;

    int start = g_offsets[w];
    int cnt   = g_offsets[w + 1] - start;

    float2 bv = ((const float2*)bias)[lane];
    unsigned long long acc[8];
#pragma unroll
    for (int kp = 0; kp < 4; ++kp) {
        acc[kp]     = dupf(bv.x);
        acc[4 + kp] = dupf(bv.y);
    }

    const char* zl = (const char*)g_z + lane * 8;

    for (int base = 0; base < cnt; base += 32) {
        int m = min(32, cnt - base);
        int idx = start + base + lane;
        int off = 0;
        float4 ea = make_float4(0.f, 0.f, 0.f, 0.f);
        float4 eb = make_float4(0.f, 0.f, 0.f, 0.f);
        if (lane < m) {
            off = g_srcs[idx];
            const float4* p = (const float4*)(g_efs + (size_t)idx * 8);
            ea = p[0];
            eb = p[1];
        }
        sOf[wblk][lane] = off;
        sA[wblk][lane] = ea;
        sB[wblk][lane] = eb;
        __syncwarp();

        int groups = (m + 3) >> 2;
        int last = groups - 1;

        int4 o4 = *(const int4*)&sOf[wblk][0];
        float2 z0 = *(const float2*)(zl + o4.x);
        float2 z1 = *(const float2*)(zl + o4.y);
        float2 z2 = *(const float2*)(zl + o4.z);
        float2 z3 = *(const float2*)(zl + o4.w);

        for (int g = 0; g < groups; ++g) {
            int gn = (g < last) ? g + 1 : last;
            int4 o4n = *(const int4*)&sOf[wblk][gn * 4];
            float2 y0 = *(const float2*)(zl + o4n.x);
            float2 y1 = *(const float2*)(zl + o4n.y);
            float2 y2 = *(const float2*)(zl + o4n.z);
            float2 y3 = *(const float2*)(zl + o4n.w);

#pragma unroll
            for (int j = 0; j < 4; ++j) {
                float2 zj = (j == 0) ? z0 : (j == 1) ? z1 : (j == 2) ? z2 : z3;
                int e = g * 4 + j;
                ulonglong2 eA = *(const ulonglong2*)&sA[wblk][e];
                ulonglong2 eB = *(const ulonglong2*)&sB[wblk][e];
                unsigned long long zx = dupf(zj.x);
                unsigned long long zy = dupf(zj.y);
                ffma2(acc[0], eA.x, zx);  ffma2(acc[4], eA.x, zy);
                ffma2(acc[1], eA.y, zx);  ffma2(acc[5], eA.y, zy);
                ffma2(acc[2], eB.x, zx);  ffma2(acc[6], eB.x, zy);
                ffma2(acc[3], eB.y, zx);  ffma2(acc[7], eB.y, zy);
            }
            z0 = y0; z1 = y1; z2 = y2; z3 = y3;
        }
        __syncwarp();
    }

    float* op = out + (size_t)w * 512 + 2 * lane;
#pragma unroll
    for (int kp = 0; kp < 4; ++kp) {
        float2 lo = unpack2(acc[kp]);
        float2 hi = unpack2(acc[4 + kp]);
        *(float2*)(op + (2 * kp) * 64)     = make_float2(lo.x, hi.x);
        *(float2*)(op + (2 * kp + 1) * 64) = make_float2(lo.y, hi.y);
    }
}

// ---------------------------------------------------------------------------
extern "C" void kernel_launch(void* const* d_in, const int* in_sizes, int n_in,
                              void* d_out, int out_size) {
    const float* node_feat = (const float*)d_in[0];
    const float* edge_feat = (const float*)d_in[1];
    const float* W         = (const float*)d_in[2];
    const float* b         = (const float*)d_in[3];
    const int*   src       = (const int*)d_in[4];
    const int*   dst       = (const int*)d_in[5];
    float*       out       = (float*)d_out;

    int N = in_sizes[0] / 64;
    int E = in_sizes[4];

    // one-time infra (no device memory): side stream + fork/join events
    static cudaStream_t s_side = nullptr;
    static cudaEvent_t  ev_fork = nullptr, ev_join = nullptr;
    if (s_side == nullptr) {
        if (cudaStreamCreateWithFlags(&s_side, cudaStreamNonBlocking)
                != cudaSuccess) s_side = nullptr;
        if (s_side) {
            cudaEventCreateWithFlags(&ev_fork, cudaEventDisableTiming);
            cudaEventCreateWithFlags(&ev_join, cudaEventDisableTiming);
        }
    }

    size_t scan_smem = (size_t)(N + 32) * sizeof(int);
    cudaFuncSetAttribute(scan_kernel,
                         cudaFuncAttributeMaxDynamicSharedMemorySize,
                         (int)scan_smem);

    int zb = (N + 63) / 64;

    if (s_side) {
        // fork: z-GEMM on side stream, overlapped with CSR construction
        cudaEventRecord(ev_fork, 0);
        cudaStreamWaitEvent(s_side, ev_fork, 0);
        z_kernel<<<zb, 256, 0, s_side>>>(node_feat, W, N);
        cudaEventRecord(ev_join, s_side);

        hist_kernel<<<((E + 3) / 4 + 255) / 256, 256>>>(dst, E);
        scan_kernel<<<1, 1024, scan_smem>>>(N);
        build_kernel<<<(E + 255) / 256, 256>>>(dst, src, edge_feat, E);

        cudaStreamWaitEvent(0, ev_join, 0);   // join before gather (needs z)
        gather_kernel<<<(N * 32 + 255) / 256, 256>>>(b, out, N);
    } else {
        // fallback: sequential
        z_kernel<<<zb, 256>>>(node_feat, W, N);
        hist_kernel<<<((E + 3) / 4 + 255) / 256, 256>>>(dst, E);
        scan_kernel<<<1, 1024, scan_smem>>>(N);
        build_kernel<<<(E + 255) / 256, 256>>>(dst, src, edge_feat, E);
        gather_kernel<<<(N * 32 + 255) / 256, 256>>>(b, out, N);
    }
}

// round 16
// speedup vs baseline: 1.2737x; 1.0366x over previous
#include <cuda_runtime.h>

// EfConv: out[n, k*64+o] = b[o] + sum_{e: dst[e]==n} edge_feat[e,k] * z[src[e], o]
// where z = node_feat @ W^T.
//
// Pipeline (multi-stream fork/join inside graph capture):
//   main stream : hist(+rank) -> scan -> build(atomic-free) -> [join] -> gather
//   side stream : z_kernel (GEMM) concurrent with hist+scan+build
//
// Rank trick: hist records rank[e] = atomicAdd(&counts[dst[e]],1), so build
// computes pos = offsets[dst[e]] + rank[e] with NO atomic -> no 318-cyc
// dependency chain in the scatter kernel.

#define MAX_N 50000
#define MAX_E 800000

__device__ float g_z[MAX_N * 64];
__device__ int   g_counts[MAX_N];
__device__ int   g_offsets[MAX_N + 1];
__device__ int   g_rank[MAX_E];          // per-edge rank within its dst bucket
__device__ int   g_srcs[MAX_E];          // src<<8 (byte offset of z row)
__device__ float g_efs[(size_t)MAX_E * 8];

// ---------------------------------------------------------------------------
__device__ __forceinline__ void ffma2(unsigned long long& d,
                                      unsigned long long a,
                                      unsigned long long b) {
    asm("fma.rn.f32x2 %0, %1, %2, %0;" : "+l"(d) : "l"(a), "l"(b));
}
__device__ __forceinline__ unsigned long long dupf(float v) {
    unsigned long long r;
    asm("mov.b64 %0, {%1, %1};" : "=l"(r) : "r"(__float_as_uint(v)));
    return r;
}
__device__ __forceinline__ float2 unpack2(unsigned long long v) {
    unsigned int lo, hi;
    asm("mov.b64 {%0, %1}, %2;" : "=r"(lo), "=r"(hi) : "l"(v));
    return make_float2(__uint_as_float(lo), __uint_as_float(hi));
}

// ---------------------------------------------------------------------------
// z = nf @ W^T, 64 nodes/block, thread = 4 nodes x 2 out-pairs (f32x2).
// ---------------------------------------------------------------------------
__global__ __launch_bounds__(256)
void z_kernel(const float* __restrict__ nf,
              const float* __restrict__ W, int N) {
    __shared__ float Ws[64 * 68];    // Ws[i*68+o] = W[o*64+i]
    __shared__ float nfs[64 * 64];
    int tid = threadIdx.x;

#pragma unroll
    for (int it = 0; it < 16; ++it) {
        int idx = it * 256 + tid;            // idx = o*64 + i
        int o = idx >> 6, i = idx & 63;
        Ws[i * 68 + o] = W[idx];
    }

    int nb = blockIdx.x * 64;
#pragma unroll
    for (int it = 0; it < 16; ++it) {
        int idx = it * 256 + tid;
        int n = nb + (idx >> 6);
        nfs[idx] = (n < N) ? nf[(size_t)n * 64 + (idx & 63)] : 0.0f;
    }
    __syncthreads();

    int ng = tid >> 4;        // node group 0..15
    int ow = tid & 15;        // out quad 0..15
    unsigned long long accp[4][2];
#pragma unroll
    for (int j = 0; j < 4; ++j) { accp[j][0] = 0ull; accp[j][1] = 0ull; }

#pragma unroll 4
    for (int i = 0; i < 64; ++i) {
        ulonglong2 wp = *(const ulonglong2*)(Ws + i * 68 + ow * 4);
        unsigned long long a0 = dupf(nfs[(ng * 4 + 0) * 64 + i]);
        unsigned long long a1 = dupf(nfs[(ng * 4 + 1) * 64 + i]);
        unsigned long long a2 = dupf(nfs[(ng * 4 + 2) * 64 + i]);
        unsigned long long a3 = dupf(nfs[(ng * 4 + 3) * 64 + i]);
        ffma2(accp[0][0], wp.x, a0);  ffma2(accp[0][1], wp.y, a0);
        ffma2(accp[1][0], wp.x, a1);  ffma2(accp[1][1], wp.y, a1);
        ffma2(accp[2][0], wp.x, a2);  ffma2(accp[2][1], wp.y, a2);
        ffma2(accp[3][0], wp.x, a3);  ffma2(accp[3][1], wp.y, a3);
    }

#pragma unroll
    for (int j = 0; j < 4; ++j) {
        int n = nb + ng * 4 + j;
        if (n < N)
            *(ulonglong2*)(g_z + (size_t)n * 64 + ow * 4) =
                make_ulonglong2(accp[j][0], accp[j][1]);
    }
}

// ---------------------------------------------------------------------------
// Histogram + rank recording: rank[e] = arrival index within dst bucket.
// ---------------------------------------------------------------------------
__global__ __launch_bounds__(256)
void hist_kernel(const int* __restrict__ dst, int E) {
    int t = blockIdx.x * 256 + threadIdx.x;
    int e4 = t * 4;
    if (e4 + 3 < E) {
        int4 d = *(const int4*)(dst + e4);
        int r0 = atomicAdd(&g_counts[d.x], 1);
        int r1 = atomicAdd(&g_counts[d.y], 1);
        int r2 = atomicAdd(&g_counts[d.z], 1);
        int r3 = atomicAdd(&g_counts[d.w], 1);
        *(int4*)(g_rank + e4) = make_int4(r0, r1, r2, r3);
    } else {
        for (int e = e4; e < E; ++e)
            g_rank[e] = atomicAdd(&g_counts[dst[e]], 1);
    }
}

// ---------------------------------------------------------------------------
__global__ __launch_bounds__(1024)
void scan_kernel(int N) {
    extern __shared__ int ss[];
    int* s     = ss;          // [N]
    int* wsum  = ss + N;      // [32]
    int t    = threadIdx.x;
    int lane = t & 31;
    int wid  = t >> 5;
    int C = (N + 1023) >> 10;

    for (int i = t; i < N; i += 1024) {
        s[i] = g_counts[i];
        g_counts[i] = 0;
    }
    __syncthreads();

    int base = t * C;
    int sum = 0;
    for (int i = 0; i < C; ++i) {
        int n = base + i;
        if (n < N) sum += s[n];
    }

    int v = sum;
#pragma unroll
    for (int d = 1; d < 32; d <<= 1) {
        int u = __shfl_up_sync(0xffffffffu, v, d);
        if (lane >= d) v += u;
    }
    if (lane == 31) wsum[wid] = v;
    __syncthreads();

    if (wid == 0) {
        int wv = wsum[lane];
#pragma unroll
        for (int d = 1; d < 32; d <<= 1) {
            int u = __shfl_up_sync(0xffffffffu, wv, d);
            if (lane >= d) wv += u;
        }
        wsum[lane] = wv;
    }
    __syncthreads();

    int excl = v - sum + (wid > 0 ? wsum[wid - 1] : 0);
    int total = wsum[31];

    int run = excl;
    for (int i = 0; i < C; ++i) {
        int n = base + i;
        if (n < N) {
            int c = s[n];
            s[n] = run;
            run += c;
        }
    }
    __syncthreads();

    for (int i = t; i < N; i += 1024)
        g_offsets[i] = s[i];
    if (t == 0) g_offsets[N] = total;
}

// ---------------------------------------------------------------------------
// Atomic-free scatter: pos = offsets[dst[e]] + rank[e]. One edge per thread.
// ---------------------------------------------------------------------------
__global__ __launch_bounds__(256)
void build_kernel(const int* __restrict__ dst,
                  const int* __restrict__ src,
                  const float* __restrict__ ef, int E) {
    int e = blockIdx.x * 256 + threadIdx.x;
    if (e < E) {
        int d = dst[e];
        int r = g_rank[e];
        int s = src[e];
        const float4* p = (const float4*)(ef + (size_t)e * 8);
        float4 a = p[0];
        float4 c = p[1];
        int pos = g_offsets[d] + r;
        g_srcs[pos] = s << 8;
        float4* q = (float4*)(g_efs + (size_t)pos * 8);
        q[0] = a;
        q[1] = c;
    }
}

// ---------------------------------------------------------------------------
// Warp per node (R8-best). acc[kp] = (out[2kp][c0], out[2kp+1][c0]) packed
// f32x2, acc[4+kp] for c1, (c0,c1)=(2*lane,2*lane+1). Per 32-edge batch:
// lane-parallel resolve into conflict-free smem; inner loop over 4-edge
// groups with z loads pipelined one group ahead.
// ---------------------------------------------------------------------------
__global__ __launch_bounds__(256)
void gather_kernel(const float* __restrict__ bias,
                   float* __restrict__ out, int N) {
    __shared__ __align__(16) float4 sA[8][32];
    __shared__ __align__(16) float4 sB[8][32];
    __shared__ __align__(16) int sOf[8][32];
    int wblk = threadIdx.x >> 5;
    int w    = (blockIdx.x * blockDim.x + threadIdx.x) >> 5;
    int lane = threadIdx.x & 31;
    if (w >= N) return;

    int start = g_offsets[w];
    int cnt   = g_offsets[w + 1] - start;

    float2 bv = ((const float2*)bias)[lane];
    unsigned long long acc[8];
#pragma unroll
    for (int kp = 0; kp < 4; ++kp) {
        acc[kp]     = dupf(bv.x);
        acc[4 + kp] = dupf(bv.y);
    }

    const char* zl = (const char*)g_z + lane * 8;

    for (int base = 0; base < cnt; base += 32) {
        int m = min(32, cnt - base);
        int idx = start + base + lane;
        int off = 0;
        float4 ea = make_float4(0.f, 0.f, 0.f, 0.f);
        float4 eb = make_float4(0.f, 0.f, 0.f, 0.f);
        if (lane < m) {
            off = g_srcs[idx];
            const float4* p = (const float4*)(g_efs + (size_t)idx * 8);
            ea = p[0];
            eb = p[1];
        }
        sOf[wblk][lane] = off;
        sA[wblk][lane] = ea;
        sB[wblk][lane] = eb;
        __syncwarp();

        int groups = (m + 3) >> 2;
        int last = groups - 1;

        int4 o4 = *(const int4*)&sOf[wblk][0];
        float2 z0 = *(const float2*)(zl + o4.x);
        float2 z1 = *(const float2*)(zl + o4.y);
        float2 z2 = *(const float2*)(zl + o4.z);
        float2 z3 = *(const float2*)(zl + o4.w);

        for (int g = 0; g < groups; ++g) {
            int gn = (g < last) ? g + 1 : last;
            int4 o4n = *(const int4*)&sOf[wblk][gn * 4];
            float2 y0 = *(const float2*)(zl + o4n.x);
            float2 y1 = *(const float2*)(zl + o4n.y);
            float2 y2 = *(const float2*)(zl + o4n.z);
            float2 y3 = *(const float2*)(zl + o4n.w);

#pragma unroll
            for (int j = 0; j < 4; ++j) {
                float2 zj = (j == 0) ? z0 : (j == 1) ? z1 : (j == 2) ? z2 : z3;
                int e = g * 4 + j;
                ulonglong2 eA = *(const ulonglong2*)&sA[wblk][e];
                ulonglong2 eB = *(const ulonglong2*)&sB[wblk][e];
                unsigned long long zx = dupf(zj.x);
                unsigned long long zy = dupf(zj.y);
                ffma2(acc[0], eA.x, zx);  ffma2(acc[4], eA.x, zy);
                ffma2(acc[1], eA.y, zx);  ffma2(acc[5], eA.y, zy);
                ffma2(acc[2], eB.x, zx);  ffma2(acc[6], eB.x, zy);
                ffma2(acc[3], eB.y, zx);  ffma2(acc[7], eB.y, zy);
            }
            z0 = y0; z1 = y1; z2 = y2; z3 = y3;
        }
        __syncwarp();
    }

    float* op = out + (size_t)w * 512 + 2 * lane;
#pragma unroll
    for (int kp = 0; kp < 4; ++kp) {
        float2 lo = unpack2(acc[kp]);
        float2 hi = unpack2(acc[4 + kp]);
        *(float2*)(op + (2 * kp) * 64)     = make_float2(lo.x, hi.x);
        *(float2*)(op + (2 * kp + 1) * 64) = make_float2(lo.y, hi.y);
    }
}

// ---------------------------------------------------------------------------
extern "C" void kernel_launch(void* const* d_in, const int* in_sizes, int n_in,
                              void* d_out, int out_size) {
    const float* node_feat = (const float*)d_in[0];
    const float* edge_feat = (const float*)d_in[1];
    const float* W         = (const float*)d_in[2];
    const float* b         = (const float*)d_in[3];
    const int*   src       = (const int*)d_in[4];
    const int*   dst       = (const int*)d_in[5];
    float*       out       = (float*)d_out;

    int N = in_sizes[0] / 64;
    int E = in_sizes[4];

    // one-time infra (no device memory): side stream + fork/join events
    static cudaStream_t s_side = nullptr;
    static cudaEvent_t  ev_fork = nullptr, ev_join = nullptr;
    if (s_side == nullptr) {
        if (cudaStreamCreateWithFlags(&s_side, cudaStreamNonBlocking)
                != cudaSuccess) s_side = nullptr;
        if (s_side) {
            cudaEventCreateWithFlags(&ev_fork, cudaEventDisableTiming);
            cudaEventCreateWithFlags(&ev_join, cudaEventDisableTiming);
        }
    }

    size_t scan_smem = (size_t)(N + 32) * sizeof(int);
    cudaFuncSetAttribute(scan_kernel,
                         cudaFuncAttributeMaxDynamicSharedMemorySize,
                         (int)scan_smem);

    int zb = (N + 63) / 64;

    if (s_side) {
        // fork: z-GEMM on side stream, overlapped with CSR construction
        cudaEventRecord(ev_fork, 0);
        cudaStreamWaitEvent(s_side, ev_fork, 0);
        z_kernel<<<zb, 256, 0, s_side>>>(node_feat, W, N);
        cudaEventRecord(ev_join, s_side);

        hist_kernel<<<((E + 3) / 4 + 255) / 256, 256>>>(dst, E);
        scan_kernel<<<1, 1024, scan_smem>>>(N);
        build_kernel<<<(E + 255) / 256, 256>>>(dst, src, edge_feat, E);

        cudaStreamWaitEvent(0, ev_join, 0);   // join before gather (needs z)
        gather_kernel<<<(N * 32 + 255) / 256, 256>>>(b, out, N);
    } else {
        // fallback: sequential
        z_kernel<<<zb, 256>>>(node_feat, W, N);
        hist_kernel<<<((E + 3) / 4 + 255) / 256, 256>>>(dst, E);
        scan_kernel<<<1, 1024, scan_smem>>>(N);
        build_kernel<<<(E + 255) / 256, 256>>>(dst, src, edge_feat, E);
        gather_kernel<<<(N * 32 + 255) / 256, 256>>>(b, out, N);
    }
}